// round 11
// baseline (speedup 1.0000x reference)
#include <cuda_runtime.h>
#include <cuda_bf16.h>
#include <math.h>
#include <cstdint>

#define NB   100
#define NC   512
#define NHW  256
#define CHW  (NC*NHW)          // 131072
#define WAYN 5
#define SHOTN 5
#define NQ   75
#define SCALEF 10.0f
#define EPSF 1e-8f

// Scratch (static device globals — no runtime allocation)
__device__ float g_M[NB*CHW];                 // exp(conv logits + bias)
__device__ float g_part[NB*8];                // per-tile partial sum(exp)
__device__ float g_s[WAYN*NC];                // prototypes
__device__ float g_sc[NQ*6*4*256];            // scores partials [n][j][ds][f]
__device__ __nv_bfloat16 g_Wh[NC*NC];         // W (bf16)
__device__ __nv_bfloat16 g_xh[NB*CHW];        // x (bf16)

// ---------------------------------------------------------------------------
// bf16 conversion kernels
// ---------------------------------------------------------------------------
__device__ __forceinline__ uint32_t pack_bf2(__nv_bfloat16 a, __nv_bfloat16 b) {
    return (uint32_t)__bfloat16_as_ushort(a) | ((uint32_t)__bfloat16_as_ushort(b) << 16);
}

__global__ void split_w(const float* __restrict__ Wm) {
    int i = (blockIdx.x * 256 + threadIdx.x) * 4;
    float4 v = *(const float4*)(Wm + i);
    uint2 ph = {pack_bf2(__float2bfloat16(v.x), __float2bfloat16(v.y)),
                pack_bf2(__float2bfloat16(v.z), __float2bfloat16(v.w))};
    *(uint2*)(g_Wh + i) = ph;
}

__global__ void split_x(const float* __restrict__ x) {
    size_t i = ((size_t)blockIdx.x * 256 + threadIdx.x) * 4;
    float4 v = *(const float4*)(x + i);
    uint2 ph = {pack_bf2(__float2bfloat16(v.x), __float2bfloat16(v.y)),
                pack_bf2(__float2bfloat16(v.z), __float2bfloat16(v.w))};
    *(uint2*)(g_xh + i) = ph;
}

// ---------------------------------------------------------------------------
// 1) Pure bf16 mma.sync GEMM, K = 512. 3-stage cp.async pipeline.
//    CTA tile 128(M) x 128(N) x 32(K), 8 warps (2m x 4n), warp tile 64x32.
//    Epilogue stores exp(logit+bias) and per-tile partial sums.
// ---------------------------------------------------------------------------
#define KCHUNK   32
#define NCHUNKS  16   // 512 / 32
#define AS_STRIDE 56
#define BS_STRIDE 136
#define AS_BYTES  (128 * AS_STRIDE * 2)      // 14336
#define BS_BYTES  (32 * BS_STRIDE * 2)       // 8704
#define STAGE_BYTES (AS_BYTES + BS_BYTES)    // 23040
#define GEMM_SMEM (3 * STAGE_BYTES)          // 69120

__global__ void __launch_bounds__(256) gemm_tc(const float* __restrict__ bias) {
    extern __shared__ __align__(16) char dynsmem[];

    const int tid = threadIdx.x;
    const int wid = tid >> 5, lid = tid & 31;
    const int bn = blockIdx.x * 128;      // n tile offset (hw)
    const int mo = blockIdx.y * 128;      // m tile offset (outC)
    const int b  = blockIdx.z;

    const int warp_m = wid >> 2;          // 0..1
    const int warp_n = wid & 3;           // 0..3
    const int m_base = warp_m * 64;
    const int n_base = warp_n * 32;

    const __nv_bfloat16* xh_b = g_xh + (size_t)b * CHW;

    float acc[4][4][4] = {};

    auto issue = [&](int chunk, int buf) {
        const int k0 = chunk * KCHUNK;
        __nv_bfloat16* As = (__nv_bfloat16*)(dynsmem + buf * STAGE_BYTES);
        __nv_bfloat16* Bs = (__nv_bfloat16*)(dynsmem + buf * STAGE_BYTES + AS_BYTES);
        #pragma unroll
        for (int i = 0; i < 2; i++) {           // A: 128 rows x 32 k
            int idx = tid + i * 256;
            int row = idx >> 2, s = idx & 3;
            const void* src = g_Wh + (size_t)(mo + row) * NC + k0 + s * 8;
            uint32_t dst = (uint32_t)__cvta_generic_to_shared(As + row * AS_STRIDE + s * 8);
            asm volatile("cp.async.cg.shared.global [%0], [%1], 16;" :: "r"(dst), "l"(src));
        }
        #pragma unroll
        for (int i = 0; i < 2; i++) {           // B: 32 k-rows x 128 n
            int idx = tid + i * 256;
            int row = idx >> 4, s = idx & 15;
            const void* src = xh_b + (size_t)(k0 + row) * NHW + bn + s * 8;
            uint32_t dst = (uint32_t)__cvta_generic_to_shared(Bs + row * BS_STRIDE + s * 8);
            asm volatile("cp.async.cg.shared.global [%0], [%1], 16;" :: "r"(dst), "l"(src));
        }
        asm volatile("cp.async.commit_group;");
    };

    issue(0, 0);
    issue(1, 1);

    int buf = 0;
    for (int c = 0; c < NCHUNKS; c++) {
        if (c == NCHUNKS - 1) asm volatile("cp.async.wait_group 0;");
        else                  asm volatile("cp.async.wait_group 1;");
        __syncthreads();
        if (c + 2 < NCHUNKS) {
            int nb = buf + 2; if (nb >= 3) nb -= 3;
            issue(c + 2, nb);
        }

        const __nv_bfloat16* As = (const __nv_bfloat16*)(dynsmem + buf * STAGE_BYTES);
        const __nv_bfloat16* Bs = (const __nv_bfloat16*)(dynsmem + buf * STAGE_BYTES + AS_BYTES);

        #pragma unroll
        for (int kk = 0; kk < 2; kk++) {
            const int k16 = kk * 16;
            uint32_t af[4][4];
            #pragma unroll
            for (int mi = 0; mi < 4; mi++) {
                uint32_t addr = (uint32_t)__cvta_generic_to_shared(
                    As + (m_base + mi * 16 + (lid & 15)) * AS_STRIDE + k16 + (lid >> 4) * 8);
                asm volatile("ldmatrix.sync.aligned.m8n8.x4.shared.b16 {%0,%1,%2,%3}, [%4];"
                    : "=r"(af[mi][0]), "=r"(af[mi][1]), "=r"(af[mi][2]), "=r"(af[mi][3])
                    : "r"(addr));
            }
            uint32_t bfr[4][2];
            #pragma unroll
            for (int njp = 0; njp < 2; njp++) {
                uint32_t addr = (uint32_t)__cvta_generic_to_shared(
                    Bs + (k16 + (lid & 15)) * BS_STRIDE + n_base + njp * 16 + (lid >> 4) * 8);
                asm volatile("ldmatrix.sync.aligned.m8n8.x4.trans.shared.b16 {%0,%1,%2,%3}, [%4];"
                    : "=r"(bfr[2*njp][0]), "=r"(bfr[2*njp][1]),
                      "=r"(bfr[2*njp+1][0]), "=r"(bfr[2*njp+1][1])
                    : "r"(addr));
            }
            #pragma unroll
            for (int mi = 0; mi < 4; mi++)
                #pragma unroll
                for (int nj = 0; nj < 4; nj++)
                    asm volatile(
                        "mma.sync.aligned.m16n8k16.row.col.f32.bf16.bf16.f32 "
                        "{%0,%1,%2,%3}, {%4,%5,%6,%7}, {%8,%9}, {%0,%1,%2,%3};"
                        : "+f"(acc[mi][nj][0]), "+f"(acc[mi][nj][1]),
                          "+f"(acc[mi][nj][2]), "+f"(acc[mi][nj][3])
                        : "r"(af[mi][0]), "r"(af[mi][1]), "r"(af[mi][2]), "r"(af[mi][3]),
                          "r"(bfr[nj][0]), "r"(bfr[nj][1]));
        }
        buf++; if (buf == 3) buf = 0;
    }

    // Epilogue: store exp(logit + bias), fused partial sum(exp)
    float* Mb = g_M + (size_t)b * CHW;
    float esum = 0.f;
    #pragma unroll
    for (int mi = 0; mi < 4; mi++) {
        int r0 = mo + m_base + mi * 16 + (lid >> 2);
        float b0 = bias[r0], b1 = bias[r0 + 8];
        #pragma unroll
        for (int nj = 0; nj < 4; nj++) {
            int col = bn + n_base + nj * 8 + (lid & 3) * 2;
            float e00 = __expf(acc[mi][nj][0] + b0);
            float e01 = __expf(acc[mi][nj][1] + b0);
            float e10 = __expf(acc[mi][nj][2] + b1);
            float e11 = __expf(acc[mi][nj][3] + b1);
            esum += e00 + e01 + e10 + e11;
            *(float2*)(Mb + (size_t)r0 * NHW + col) = make_float2(e00, e01);
            *(float2*)(Mb + (size_t)(r0 + 8) * NHW + col) = make_float2(e10, e11);
        }
    }
    __syncthreads();                 // all async groups done; safe to reuse smem
    float* red = (float*)dynsmem;
    red[tid] = esum;
    __syncthreads();
    for (int s = 128; s > 0; s >>= 1) {
        if (tid < s) red[tid] += red[tid + s];
        __syncthreads();
    }
    if (tid == 0)
        g_part[b * 8 + blockIdx.y * 2 + blockIdx.x] = red[0];
}

// ---------------------------------------------------------------------------
// 2) Prototypes (fused mask): s[m,d] = mean over shots,hw of x*Me*inv_sb
//    320 threads: one float4 per thread (5 shots x 64 float4s), shfl reduce.
// ---------------------------------------------------------------------------
__global__ void __launch_bounds__(320) protos(const float* __restrict__ x) {
    __shared__ float inv_sm[SHOTN];
    __shared__ float wsum[10];
    const int m = blockIdx.x;
    const int d = blockIdx.y;
    const int tid = threadIdx.x;

    if (tid < SHOTN) {
        float s = 0.f;
        #pragma unroll
        for (int t = 0; t < 8; t++) s += g_part[(m * 20 + tid) * 8 + t];
        inv_sm[tid] = 1.f / s;
    }
    __syncthreads();

    const int sb = tid >> 6;           // 0..4
    const int q  = tid & 63;           // 0..63 (float4 index)
    const size_t base = (size_t)(m * 20 + sb) * CHW + (size_t)d * NHW + q * 4;
    float4 xv = *(const float4*)(x + base);
    float4 mv = *(const float4*)(g_M + base);
    float s = (xv.x * mv.x + xv.y * mv.y + xv.z * mv.z + xv.w * mv.w) * inv_sm[sb];

    #pragma unroll
    for (int o = 16; o > 0; o >>= 1)
        s += __shfl_xor_sync(0xffffffff, s, o);
    if ((tid & 31) == 0) wsum[tid >> 5] = s;
    __syncthreads();
    if (tid == 0) {
        float t = 0.f;
        #pragma unroll
        for (int w = 0; w < 10; w++) t += wsum[w];
        g_s[m * NC + d] = t * (1.f / (SHOTN * NHW));
    }
}

// ---------------------------------------------------------------------------
// 3a) Scores partials: grid (NQ, 4); block (n, ds) handles 128 d-rows.
//     qv = x * exp(M)  (mask normalizer cancels in cosine).
//     Writes q2 / dot[m] partials per f to g_sc[n][j][ds][f].
// ---------------------------------------------------------------------------
__global__ void __launch_bounds__(256) scores_part(const float* __restrict__ x) {
    __shared__ float s_sm[WAYN * 128];       // prototype slice for this d-quarter

    const int n  = blockIdx.x;
    const int ds = blockIdx.y;               // 0..3
    const int m0 = n / 15;
    const int qi = n - m0 * 15;
    const int bq = m0 * 20 + SHOTN + qi;
    const int tid = threadIdx.x;
    const int d0 = ds * 128;

    for (int l = tid; l < WAYN * 128; l += 256) {
        int m = l >> 7, dd = l & 127;
        s_sm[l] = g_s[m * NC + d0 + dd];
    }
    __syncthreads();

    const int f = tid;
    const float* xb = x + (size_t)bq * CHW;
    const float* Mb = g_M + (size_t)bq * CHW;

    float dot[WAYN] = {};
    float q2 = 0.f;
    #pragma unroll 4
    for (int dd = 0; dd < 128; dd++) {
        size_t idx = (size_t)(d0 + dd) * NHW + f;
        float qv = xb[idx] * Mb[idx];
        q2 += qv * qv;
        #pragma unroll
        for (int m = 0; m < WAYN; m++)
            dot[m] += qv * s_sm[m * 128 + dd];
    }

    float* o = g_sc + ((size_t)n * 6 * 4 + ds) * 256 + f;
    o[0] = q2;
    #pragma unroll
    for (int m = 0; m < WAYN; m++) o[(size_t)(1 + m) * 4 * 256] = dot[m];
}

// ---------------------------------------------------------------------------
// 3b) Scores finisher: combine partials, proto norms, softmax, spatial mean.
// ---------------------------------------------------------------------------
__global__ void __launch_bounds__(256) scores_fin(float* __restrict__ out) {
    __shared__ float s_sm[WAYN * NC];
    __shared__ float sn_sm[WAYN];
    __shared__ float red[256];

    const int n = blockIdx.x;
    const int tid = threadIdx.x;

    for (int l = tid; l < WAYN * NC; l += 256) s_sm[l] = g_s[l];
    __syncthreads();

    const int wid = tid >> 5, lid = tid & 31;
    if (wid < WAYN) {
        float a = 0.f;
        #pragma unroll
        for (int j = 0; j < NC / 32; j++) {
            float v = s_sm[wid * NC + j * 32 + lid];
            a += v * v;
        }
        #pragma unroll
        for (int o = 16; o > 0; o >>= 1)
            a += __shfl_xor_sync(0xffffffff, a, o);
        if (lid == 0) sn_sm[wid] = fmaxf(sqrtf(a), EPSF);
    }
    __syncthreads();

    const int f = tid;
    const float* base = g_sc + (size_t)n * 6 * 4 * 256 + f;
    float q2 = base[0] + base[256] + base[512] + base[768];
    float dot[WAYN];
    #pragma unroll
    for (int m = 0; m < WAYN; m++) {
        const float* bm = base + (size_t)(1 + m) * 4 * 256;
        dot[m] = bm[0] + bm[256] + bm[512] + bm[768];
    }

    const float qn = fmaxf(sqrtf(q2), EPSF);
    float sc[WAYN], mxv = -3.4e38f;
    #pragma unroll
    for (int m = 0; m < WAYN; m++) {
        sc[m] = SCALEF * dot[m] / (qn * sn_sm[m]);
        mxv = fmaxf(mxv, sc[m]);
    }
    float eprob[WAYN], ssum = 0.f;
    #pragma unroll
    for (int m = 0; m < WAYN; m++) { eprob[m] = __expf(sc[m] - mxv); ssum += eprob[m]; }
    const float inv = 1.f / ssum;

    for (int m = 0; m < WAYN; m++) {
        red[tid] = eprob[m] * inv;
        __syncthreads();
        for (int st = 128; st > 0; st >>= 1) {
            if (tid < st) red[tid] += red[tid + st];
            __syncthreads();
        }
        if (tid == 0) out[n * WAYN + m] = red[0] * (1.f / NHW);
        __syncthreads();
    }
}

// ---------------------------------------------------------------------------
extern "C" void kernel_launch(void* const* d_in, const int* in_sizes, int n_in,
                              void* d_out, int out_size) {
    const float* x    = (const float*)d_in[0];   // (100, 512, 16, 16)
    const float* Wm   = (const float*)d_in[1];   // (512, 512)
    const float* bias = (const float*)d_in[2];   // (512,)
    float* out = (float*)d_out;                  // (75, 5)

    static int smem_set = 0;
    if (!smem_set) {
        cudaFuncSetAttribute(gemm_tc, cudaFuncAttributeMaxDynamicSharedMemorySize, GEMM_SMEM);
        smem_set = 1;
    }

    split_w<<<NC * NC / 1024, 256>>>(Wm);
    split_x<<<NB * CHW / 1024, 256>>>(x);
    gemm_tc<<<dim3(NHW / 128, NC / 128, NB), 256, GEMM_SMEM>>>(bias);
    protos<<<dim3(WAYN, NC), 320>>>(x);                 // 4th launch -> ncu target
    scores_part<<<dim3(NQ, 4), 256>>>(x);
    scores_fin<<<NQ, 256>>>(out);
}

// round 12
// speedup vs baseline: 1.6028x; 1.6028x over previous
#include <cuda_runtime.h>
#include <cuda_bf16.h>
#include <math.h>
#include <cstdint>

#define NB   100
#define NC   512
#define NHW  256
#define CHW  (NC*NHW)          // 131072
#define WAYN 5
#define SHOTN 5
#define NQ   75
#define SCALEF 10.0f
#define EPSF 1e-8f

// Scratch (static device globals — no runtime allocation)
__device__ float g_M[NB*CHW];                 // exp(conv logits + bias)
__device__ float g_part[NB*8];                // per-tile partial sum(exp)
__device__ float g_s[WAYN*NC];                // prototypes
__device__ __nv_bfloat16 g_Wh[NC*NC];         // W (bf16)
__device__ __nv_bfloat16 g_xh[NB*CHW];        // x (bf16)

// ---------------------------------------------------------------------------
// bf16 conversion kernels
// ---------------------------------------------------------------------------
__device__ __forceinline__ uint32_t pack_bf2(__nv_bfloat16 a, __nv_bfloat16 b) {
    return (uint32_t)__bfloat16_as_ushort(a) | ((uint32_t)__bfloat16_as_ushort(b) << 16);
}

__global__ void split_w(const float* __restrict__ Wm) {
    int i = (blockIdx.x * 256 + threadIdx.x) * 4;
    float4 v = *(const float4*)(Wm + i);
    uint2 ph = {pack_bf2(__float2bfloat16(v.x), __float2bfloat16(v.y)),
                pack_bf2(__float2bfloat16(v.z), __float2bfloat16(v.w))};
    *(uint2*)(g_Wh + i) = ph;
}

__global__ void split_x(const float* __restrict__ x) {
    size_t i = ((size_t)blockIdx.x * 256 + threadIdx.x) * 4;
    float4 v = *(const float4*)(x + i);
    uint2 ph = {pack_bf2(__float2bfloat16(v.x), __float2bfloat16(v.y)),
                pack_bf2(__float2bfloat16(v.z), __float2bfloat16(v.w))};
    *(uint2*)(g_xh + i) = ph;
}

// ---------------------------------------------------------------------------
// 1) Pure bf16 mma.sync GEMM, K = 512. 3-stage cp.async pipeline.
//    CTA tile 128(M) x 128(N) x 32(K), 8 warps (2m x 4n), warp tile 64x32.
//    Epilogue stores exp(logit+bias) and per-tile partial sums.
// ---------------------------------------------------------------------------
#define KCHUNK   32
#define NCHUNKS  16   // 512 / 32
#define AS_STRIDE 56
#define BS_STRIDE 136
#define AS_BYTES  (128 * AS_STRIDE * 2)      // 14336
#define BS_BYTES  (32 * BS_STRIDE * 2)       // 8704
#define STAGE_BYTES (AS_BYTES + BS_BYTES)    // 23040
#define GEMM_SMEM (3 * STAGE_BYTES)          // 69120

__global__ void __launch_bounds__(256) gemm_tc(const float* __restrict__ bias) {
    extern __shared__ __align__(16) char dynsmem[];

    const int tid = threadIdx.x;
    const int wid = tid >> 5, lid = tid & 31;
    const int bn = blockIdx.x * 128;      // n tile offset (hw)
    const int mo = blockIdx.y * 128;      // m tile offset (outC)
    const int b  = blockIdx.z;

    const int warp_m = wid >> 2;          // 0..1
    const int warp_n = wid & 3;           // 0..3
    const int m_base = warp_m * 64;
    const int n_base = warp_n * 32;

    const __nv_bfloat16* xh_b = g_xh + (size_t)b * CHW;

    float acc[4][4][4] = {};

    auto issue = [&](int chunk, int buf) {
        const int k0 = chunk * KCHUNK;
        __nv_bfloat16* As = (__nv_bfloat16*)(dynsmem + buf * STAGE_BYTES);
        __nv_bfloat16* Bs = (__nv_bfloat16*)(dynsmem + buf * STAGE_BYTES + AS_BYTES);
        #pragma unroll
        for (int i = 0; i < 2; i++) {           // A: 128 rows x 32 k
            int idx = tid + i * 256;
            int row = idx >> 2, s = idx & 3;
            const void* src = g_Wh + (size_t)(mo + row) * NC + k0 + s * 8;
            uint32_t dst = (uint32_t)__cvta_generic_to_shared(As + row * AS_STRIDE + s * 8);
            asm volatile("cp.async.cg.shared.global [%0], [%1], 16;" :: "r"(dst), "l"(src));
        }
        #pragma unroll
        for (int i = 0; i < 2; i++) {           // B: 32 k-rows x 128 n
            int idx = tid + i * 256;
            int row = idx >> 4, s = idx & 15;
            const void* src = xh_b + (size_t)(k0 + row) * NHW + bn + s * 8;
            uint32_t dst = (uint32_t)__cvta_generic_to_shared(Bs + row * BS_STRIDE + s * 8);
            asm volatile("cp.async.cg.shared.global [%0], [%1], 16;" :: "r"(dst), "l"(src));
        }
        asm volatile("cp.async.commit_group;");
    };

    issue(0, 0);
    issue(1, 1);

    int buf = 0;
    for (int c = 0; c < NCHUNKS; c++) {
        if (c == NCHUNKS - 1) asm volatile("cp.async.wait_group 0;");
        else                  asm volatile("cp.async.wait_group 1;");
        __syncthreads();
        if (c + 2 < NCHUNKS) {
            int nb = buf + 2; if (nb >= 3) nb -= 3;
            issue(c + 2, nb);
        }

        const __nv_bfloat16* As = (const __nv_bfloat16*)(dynsmem + buf * STAGE_BYTES);
        const __nv_bfloat16* Bs = (const __nv_bfloat16*)(dynsmem + buf * STAGE_BYTES + AS_BYTES);

        #pragma unroll
        for (int kk = 0; kk < 2; kk++) {
            const int k16 = kk * 16;
            uint32_t af[4][4];
            #pragma unroll
            for (int mi = 0; mi < 4; mi++) {
                uint32_t addr = (uint32_t)__cvta_generic_to_shared(
                    As + (m_base + mi * 16 + (lid & 15)) * AS_STRIDE + k16 + (lid >> 4) * 8);
                asm volatile("ldmatrix.sync.aligned.m8n8.x4.shared.b16 {%0,%1,%2,%3}, [%4];"
                    : "=r"(af[mi][0]), "=r"(af[mi][1]), "=r"(af[mi][2]), "=r"(af[mi][3])
                    : "r"(addr));
            }
            uint32_t bfr[4][2];
            #pragma unroll
            for (int njp = 0; njp < 2; njp++) {
                uint32_t addr = (uint32_t)__cvta_generic_to_shared(
                    Bs + (k16 + (lid & 15)) * BS_STRIDE + n_base + njp * 16 + (lid >> 4) * 8);
                asm volatile("ldmatrix.sync.aligned.m8n8.x4.trans.shared.b16 {%0,%1,%2,%3}, [%4];"
                    : "=r"(bfr[2*njp][0]), "=r"(bfr[2*njp][1]),
                      "=r"(bfr[2*njp+1][0]), "=r"(bfr[2*njp+1][1])
                    : "r"(addr));
            }
            #pragma unroll
            for (int mi = 0; mi < 4; mi++)
                #pragma unroll
                for (int nj = 0; nj < 4; nj++)
                    asm volatile(
                        "mma.sync.aligned.m16n8k16.row.col.f32.bf16.bf16.f32 "
                        "{%0,%1,%2,%3}, {%4,%5,%6,%7}, {%8,%9}, {%0,%1,%2,%3};"
                        : "+f"(acc[mi][nj][0]), "+f"(acc[mi][nj][1]),
                          "+f"(acc[mi][nj][2]), "+f"(acc[mi][nj][3])
                        : "r"(af[mi][0]), "r"(af[mi][1]), "r"(af[mi][2]), "r"(af[mi][3]),
                          "r"(bfr[nj][0]), "r"(bfr[nj][1]));
        }
        buf++; if (buf == 3) buf = 0;
    }

    // Epilogue: store exp(logit + bias), fused partial sum(exp)
    float* Mb = g_M + (size_t)b * CHW;
    float esum = 0.f;
    #pragma unroll
    for (int mi = 0; mi < 4; mi++) {
        int r0 = mo + m_base + mi * 16 + (lid >> 2);
        float b0 = bias[r0], b1 = bias[r0 + 8];
        #pragma unroll
        for (int nj = 0; nj < 4; nj++) {
            int col = bn + n_base + nj * 8 + (lid & 3) * 2;
            float e00 = __expf(acc[mi][nj][0] + b0);
            float e01 = __expf(acc[mi][nj][1] + b0);
            float e10 = __expf(acc[mi][nj][2] + b1);
            float e11 = __expf(acc[mi][nj][3] + b1);
            esum += e00 + e01 + e10 + e11;
            *(float2*)(Mb + (size_t)r0 * NHW + col) = make_float2(e00, e01);
            *(float2*)(Mb + (size_t)(r0 + 8) * NHW + col) = make_float2(e10, e11);
        }
    }
    __syncthreads();                 // all async groups done; safe to reuse smem
    float* red = (float*)dynsmem;
    red[tid] = esum;
    __syncthreads();
    for (int s = 128; s > 0; s >>= 1) {
        if (tid < s) red[tid] += red[tid + s];
        __syncthreads();
    }
    if (tid == 0)
        g_part[b * 8 + blockIdx.y * 2 + blockIdx.x] = red[0];
}

// ---------------------------------------------------------------------------
// 2) Prototypes (fused mask): s[m,d] = mean over shots,hw of x*Me*inv_sb
//    320 threads: one float4 per thread (5 shots x 64 float4s), shfl reduce.
// ---------------------------------------------------------------------------
__global__ void __launch_bounds__(320) protos(const float* __restrict__ x) {
    __shared__ float inv_sm[SHOTN];
    __shared__ float wsum[10];
    const int m = blockIdx.x;
    const int d = blockIdx.y;
    const int tid = threadIdx.x;

    if (tid < SHOTN) {
        float s = 0.f;
        #pragma unroll
        for (int t = 0; t < 8; t++) s += g_part[(m * 20 + tid) * 8 + t];
        inv_sm[tid] = 1.f / s;
    }
    __syncthreads();

    const int sb = tid >> 6;           // 0..4
    const int q  = tid & 63;           // 0..63 (float4 index)
    const size_t base = (size_t)(m * 20 + sb) * CHW + (size_t)d * NHW + q * 4;
    float4 xv = *(const float4*)(x + base);
    float4 mv = *(const float4*)(g_M + base);
    float s = (xv.x * mv.x + xv.y * mv.y + xv.z * mv.z + xv.w * mv.w) * inv_sm[sb];

    #pragma unroll
    for (int o = 16; o > 0; o >>= 1)
        s += __shfl_xor_sync(0xffffffff, s, o);
    if ((tid & 31) == 0) wsum[tid >> 5] = s;
    __syncthreads();
    if (tid == 0) {
        float t = 0.f;
        #pragma unroll
        for (int w = 0; w < 10; w++) t += wsum[w];
        g_s[m * NC + d] = t * (1.f / (SHOTN * NHW));
    }
}

// ---------------------------------------------------------------------------
// 3) Cosine scores + class softmax + spatial mean.
//    Grid (NQ, 2): each block handles a 128-f half, all 512 d via 8 in-block
//    d-slices (smem combine). Cross-block spatial mean via 2-way atomicAdd
//    into zero-initialized out (bit-deterministic: fp add is commutative).
//    qv = x * exp(M) — mask normalizer cancels in cosine.
// ---------------------------------------------------------------------------
__global__ void __launch_bounds__(1024) scores_kernel(const float* __restrict__ x,
                                                      float* __restrict__ out) {
    __shared__ float s_sm[WAYN * NC];        // 10 KB
    __shared__ float sn_sm[WAYN];
    __shared__ float part[6][8][128];        // 24 KB
    __shared__ float red[128];

    const int n  = blockIdx.x;
    const int fh = blockIdx.y;               // 0..1 spatial half
    const int m0 = n / 15;
    const int qi = n - m0 * 15;
    const int bq = m0 * 20 + SHOTN + qi;
    const int tid = threadIdx.x;

    for (int l = tid; l < WAYN * NC; l += 1024) s_sm[l] = g_s[l];
    __syncthreads();

    // warps 0..4: warp w reduces ||s[w]||  (sn read after the next barrier)
    const int wid = tid >> 5, lid = tid & 31;
    if (wid < WAYN) {
        float a = 0.f;
        #pragma unroll
        for (int j = 0; j < NC / 32; j++) {
            float v = s_sm[wid * NC + j * 32 + lid];
            a += v * v;
        }
        #pragma unroll
        for (int o = 16; o > 0; o >>= 1)
            a += __shfl_xor_sync(0xffffffff, a, o);
        if (lid == 0) sn_sm[wid] = fmaxf(sqrtf(a), EPSF);
    }

    const int fl = tid & 127;
    const int f  = fh * 128 + fl;
    const int slice = tid >> 7;              // 0..7
    const int d0 = slice * 64;
    const float* xb = x + (size_t)bq * CHW;
    const float* Mb = g_M + (size_t)bq * CHW;

    float dot[WAYN] = {};
    float q2 = 0.f;
    #pragma unroll 4
    for (int dd = 0; dd < 64; dd++) {
        size_t idx = (size_t)(d0 + dd) * NHW + f;
        float qv = xb[idx] * Mb[idx];
        q2 += qv * qv;
        #pragma unroll
        for (int m = 0; m < WAYN; m++)
            dot[m] += qv * s_sm[m * NC + d0 + dd];
    }
    part[0][slice][fl] = q2;
    #pragma unroll
    for (int m = 0; m < WAYN; m++) part[1 + m][slice][fl] = dot[m];
    __syncthreads();

    float eprob[WAYN];
    if (slice == 0) {                        // tid < 128
        q2 = 0.f;
        #pragma unroll
        for (int s = 0; s < 8; s++) q2 += part[0][s][fl];
        #pragma unroll
        for (int m = 0; m < WAYN; m++) {
            float dsum = 0.f;
            #pragma unroll
            for (int s = 0; s < 8; s++) dsum += part[1 + m][s][fl];
            dot[m] = dsum;
        }
        const float qn = fmaxf(sqrtf(q2), EPSF);
        float sc[WAYN], mxv = -3.4e38f;
        #pragma unroll
        for (int m = 0; m < WAYN; m++) {
            sc[m] = SCALEF * dot[m] / (qn * sn_sm[m]);
            mxv = fmaxf(mxv, sc[m]);
        }
        float ssum = 0.f;
        #pragma unroll
        for (int m = 0; m < WAYN; m++) { eprob[m] = __expf(sc[m] - mxv); ssum += eprob[m]; }
        const float inv = 1.f / ssum;
        #pragma unroll
        for (int m = 0; m < WAYN; m++) eprob[m] *= inv;
    }

    for (int m = 0; m < WAYN; m++) {
        __syncthreads();
        if (slice == 0) red[fl] = eprob[m];
        __syncthreads();
        for (int st = 64; st > 0; st >>= 1) {
            if (tid < st) red[tid] += red[tid + st];
            __syncthreads();
        }
        if (tid == 0) atomicAdd(&out[n * WAYN + m], red[0] * (1.f / NHW));
    }
}

// ---------------------------------------------------------------------------
extern "C" void kernel_launch(void* const* d_in, const int* in_sizes, int n_in,
                              void* d_out, int out_size) {
    const float* x    = (const float*)d_in[0];   // (100, 512, 16, 16)
    const float* Wm   = (const float*)d_in[1];   // (512, 512)
    const float* bias = (const float*)d_in[2];   // (512,)
    float* out = (float*)d_out;                  // (75, 5)

    static int smem_set = 0;
    if (!smem_set) {
        cudaFuncSetAttribute(gemm_tc, cudaFuncAttributeMaxDynamicSharedMemorySize, GEMM_SMEM);
        smem_set = 1;
    }

    cudaMemsetAsync(out, 0, (size_t)out_size * sizeof(float));   // capturable memset node
    split_w<<<NC * NC / 1024, 256>>>(Wm);
    split_x<<<NB * CHW / 1024, 256>>>(x);
    gemm_tc<<<dim3(NHW / 128, NC / 128, NB), 256, GEMM_SMEM>>>(bias);
    protos<<<dim3(WAYN, NC), 320>>>(x);
    scores_kernel<<<dim3(NQ, 2), 1024>>>(x, out);
}

// round 13
// speedup vs baseline: 1.6195x; 1.0104x over previous
#include <cuda_runtime.h>
#include <cuda_bf16.h>
#include <math.h>
#include <cstdint>

#define NB   100
#define NC   512
#define NHW  256
#define CHW  (NC*NHW)          // 131072
#define WAYN 5
#define SHOTN 5
#define NQ   75
#define SCALEF 10.0f
#define EPSF 1e-8f

// Scratch (static device globals — no runtime allocation)
__device__ __nv_bfloat16 g_M[NB*CHW];         // exp(conv logits + bias), bf16
__device__ float g_part[NB*8];                // per-tile partial sum(exp)
__device__ float g_s[WAYN*NC];                // prototypes
__device__ __nv_bfloat16 g_Wh[NC*NC];         // W (bf16)
__device__ __nv_bfloat16 g_xh[NB*CHW];        // x (bf16)

// ---------------------------------------------------------------------------
// Fused fp32 -> bf16 conversion: blocks [0,256) do W, rest do x.
// ---------------------------------------------------------------------------
__device__ __forceinline__ uint32_t pack_bf2(__nv_bfloat16 a, __nv_bfloat16 b) {
    return (uint32_t)__bfloat16_as_ushort(a) | ((uint32_t)__bfloat16_as_ushort(b) << 16);
}

#define WBLOCKS (NC * NC / 1024)              // 256

__global__ void split_all(const float* __restrict__ x, const float* __restrict__ Wm) {
    const float* src;
    __nv_bfloat16* dst;
    size_t i;
    if (blockIdx.x < WBLOCKS) {
        i = ((size_t)blockIdx.x * 256 + threadIdx.x) * 4;
        src = Wm; dst = g_Wh;
    } else {
        i = ((size_t)(blockIdx.x - WBLOCKS) * 256 + threadIdx.x) * 4;
        src = x; dst = g_xh;
    }
    float4 v = *(const float4*)(src + i);
    uint2 ph = {pack_bf2(__float2bfloat16(v.x), __float2bfloat16(v.y)),
                pack_bf2(__float2bfloat16(v.z), __float2bfloat16(v.w))};
    *(uint2*)(dst + i) = ph;
}

// ---------------------------------------------------------------------------
// 1) Pure bf16 mma.sync GEMM, K = 512. 3-stage cp.async pipeline.
//    CTA tile 128(M) x 128(N) x 32(K), 8 warps (2m x 4n), warp tile 64x32.
//    Epilogue stores bf16 exp(logit+bias) and fp32 per-tile partial sums.
// ---------------------------------------------------------------------------
#define KCHUNK   32
#define NCHUNKS  16   // 512 / 32
#define AS_STRIDE 56
#define BS_STRIDE 136
#define AS_BYTES  (128 * AS_STRIDE * 2)      // 14336
#define BS_BYTES  (32 * BS_STRIDE * 2)       // 8704
#define STAGE_BYTES (AS_BYTES + BS_BYTES)    // 23040
#define GEMM_SMEM (3 * STAGE_BYTES)          // 69120

__global__ void __launch_bounds__(256) gemm_tc(const float* __restrict__ bias) {
    extern __shared__ __align__(16) char dynsmem[];

    const int tid = threadIdx.x;
    const int wid = tid >> 5, lid = tid & 31;
    const int bn = blockIdx.x * 128;      // n tile offset (hw)
    const int mo = blockIdx.y * 128;      // m tile offset (outC)
    const int b  = blockIdx.z;

    const int warp_m = wid >> 2;          // 0..1
    const int warp_n = wid & 3;           // 0..3
    const int m_base = warp_m * 64;
    const int n_base = warp_n * 32;

    const __nv_bfloat16* xh_b = g_xh + (size_t)b * CHW;

    float acc[4][4][4] = {};

    auto issue = [&](int chunk, int buf) {
        const int k0 = chunk * KCHUNK;
        __nv_bfloat16* As = (__nv_bfloat16*)(dynsmem + buf * STAGE_BYTES);
        __nv_bfloat16* Bs = (__nv_bfloat16*)(dynsmem + buf * STAGE_BYTES + AS_BYTES);
        #pragma unroll
        for (int i = 0; i < 2; i++) {           // A: 128 rows x 32 k
            int idx = tid + i * 256;
            int row = idx >> 2, s = idx & 3;
            const void* src = g_Wh + (size_t)(mo + row) * NC + k0 + s * 8;
            uint32_t dst = (uint32_t)__cvta_generic_to_shared(As + row * AS_STRIDE + s * 8);
            asm volatile("cp.async.cg.shared.global [%0], [%1], 16;" :: "r"(dst), "l"(src));
        }
        #pragma unroll
        for (int i = 0; i < 2; i++) {           // B: 32 k-rows x 128 n
            int idx = tid + i * 256;
            int row = idx >> 4, s = idx & 15;
            const void* src = xh_b + (size_t)(k0 + row) * NHW + bn + s * 8;
            uint32_t dst = (uint32_t)__cvta_generic_to_shared(Bs + row * BS_STRIDE + s * 8);
            asm volatile("cp.async.cg.shared.global [%0], [%1], 16;" :: "r"(dst), "l"(src));
        }
        asm volatile("cp.async.commit_group;");
    };

    issue(0, 0);
    issue(1, 1);

    int buf = 0;
    for (int c = 0; c < NCHUNKS; c++) {
        if (c == NCHUNKS - 1) asm volatile("cp.async.wait_group 0;");
        else                  asm volatile("cp.async.wait_group 1;");
        __syncthreads();
        if (c + 2 < NCHUNKS) {
            int nb = buf + 2; if (nb >= 3) nb -= 3;
            issue(c + 2, nb);
        }

        const __nv_bfloat16* As = (const __nv_bfloat16*)(dynsmem + buf * STAGE_BYTES);
        const __nv_bfloat16* Bs = (const __nv_bfloat16*)(dynsmem + buf * STAGE_BYTES + AS_BYTES);

        #pragma unroll
        for (int kk = 0; kk < 2; kk++) {
            const int k16 = kk * 16;
            uint32_t af[4][4];
            #pragma unroll
            for (int mi = 0; mi < 4; mi++) {
                uint32_t addr = (uint32_t)__cvta_generic_to_shared(
                    As + (m_base + mi * 16 + (lid & 15)) * AS_STRIDE + k16 + (lid >> 4) * 8);
                asm volatile("ldmatrix.sync.aligned.m8n8.x4.shared.b16 {%0,%1,%2,%3}, [%4];"
                    : "=r"(af[mi][0]), "=r"(af[mi][1]), "=r"(af[mi][2]), "=r"(af[mi][3])
                    : "r"(addr));
            }
            uint32_t bfr[4][2];
            #pragma unroll
            for (int njp = 0; njp < 2; njp++) {
                uint32_t addr = (uint32_t)__cvta_generic_to_shared(
                    Bs + (k16 + (lid & 15)) * BS_STRIDE + n_base + njp * 16 + (lid >> 4) * 8);
                asm volatile("ldmatrix.sync.aligned.m8n8.x4.trans.shared.b16 {%0,%1,%2,%3}, [%4];"
                    : "=r"(bfr[2*njp][0]), "=r"(bfr[2*njp][1]),
                      "=r"(bfr[2*njp+1][0]), "=r"(bfr[2*njp+1][1])
                    : "r"(addr));
            }
            #pragma unroll
            for (int mi = 0; mi < 4; mi++)
                #pragma unroll
                for (int nj = 0; nj < 4; nj++)
                    asm volatile(
                        "mma.sync.aligned.m16n8k16.row.col.f32.bf16.bf16.f32 "
                        "{%0,%1,%2,%3}, {%4,%5,%6,%7}, {%8,%9}, {%0,%1,%2,%3};"
                        : "+f"(acc[mi][nj][0]), "+f"(acc[mi][nj][1]),
                          "+f"(acc[mi][nj][2]), "+f"(acc[mi][nj][3])
                        : "r"(af[mi][0]), "r"(af[mi][1]), "r"(af[mi][2]), "r"(af[mi][3]),
                          "r"(bfr[nj][0]), "r"(bfr[nj][1]));
        }
        buf++; if (buf == 3) buf = 0;
    }

    // Epilogue: store bf16 exp(logit + bias), fused fp32 partial sum(exp)
    __nv_bfloat16* Mb = g_M + (size_t)b * CHW;
    float esum = 0.f;
    #pragma unroll
    for (int mi = 0; mi < 4; mi++) {
        int r0 = mo + m_base + mi * 16 + (lid >> 2);
        float b0 = bias[r0], b1 = bias[r0 + 8];
        #pragma unroll
        for (int nj = 0; nj < 4; nj++) {
            int col = bn + n_base + nj * 8 + (lid & 3) * 2;
            float e00 = __expf(acc[mi][nj][0] + b0);
            float e01 = __expf(acc[mi][nj][1] + b0);
            float e10 = __expf(acc[mi][nj][2] + b1);
            float e11 = __expf(acc[mi][nj][3] + b1);
            esum += e00 + e01 + e10 + e11;
            *(uint32_t*)(Mb + (size_t)r0 * NHW + col) =
                pack_bf2(__float2bfloat16(e00), __float2bfloat16(e01));
            *(uint32_t*)(Mb + (size_t)(r0 + 8) * NHW + col) =
                pack_bf2(__float2bfloat16(e10), __float2bfloat16(e11));
        }
    }
    __syncthreads();                 // all async groups done; safe to reuse smem
    float* red = (float*)dynsmem;
    red[tid] = esum;
    __syncthreads();
    for (int s = 128; s > 0; s >>= 1) {
        if (tid < s) red[tid] += red[tid + s];
        __syncthreads();
    }
    if (tid == 0)
        g_part[b * 8 + blockIdx.y * 2 + blockIdx.x] = red[0];
}

// ---------------------------------------------------------------------------
// 2) Prototypes (fused mask): s[m,d] = mean over shots,hw of x*Me*inv_sb
//    160 threads = 5 warps; warp = shot; each thread 8 bf16 pairs (uint4).
// ---------------------------------------------------------------------------
__global__ void __launch_bounds__(160) protos() {
    __shared__ float inv_sm[SHOTN];
    __shared__ float wsum[SHOTN];
    const int m = blockIdx.x;
    const int d = blockIdx.y;
    const int tid = threadIdx.x;
    const int sb = tid >> 5;           // warp = shot
    const int lid = tid & 31;

    if (tid < SHOTN) {
        float s = 0.f;
        #pragma unroll
        for (int t = 0; t < 8; t++) s += g_part[(m * 20 + tid) * 8 + t];
        inv_sm[tid] = 1.f / s;
    }
    __syncthreads();

    const size_t base = (size_t)(m * 20 + sb) * CHW + (size_t)d * NHW + lid * 8;
    uint4 xv = *(const uint4*)(g_xh + base);
    uint4 mv = *(const uint4*)(g_M + base);
    float s = 0.f;
    const uint32_t* xp = (const uint32_t*)&xv;
    const uint32_t* mp = (const uint32_t*)&mv;
    #pragma unroll
    for (int j = 0; j < 4; j++) {
        float2 xf = __bfloat1622float2(*(const __nv_bfloat162*)&xp[j]);
        float2 mf = __bfloat1622float2(*(const __nv_bfloat162*)&mp[j]);
        s += xf.x * mf.x + xf.y * mf.y;
    }
    s *= inv_sm[sb];

    #pragma unroll
    for (int o = 16; o > 0; o >>= 1)
        s += __shfl_xor_sync(0xffffffff, s, o);
    if (lid == 0) wsum[sb] = s;
    __syncthreads();
    if (tid == 0) {
        float t = 0.f;
        #pragma unroll
        for (int w = 0; w < SHOTN; w++) t += wsum[w];
        g_s[m * NC + d] = t * (1.f / (SHOTN * NHW));
    }
}

// ---------------------------------------------------------------------------
// 3) Cosine scores + class softmax + spatial mean.
//    Grid (NQ, 2), 512 threads: thread = (d-slice 0..7, f-pair 0..63).
//    qv = x * Me (bf16 inputs); mask normalizer cancels in cosine.
//    Cross-block spatial mean via 2-way atomicAdd into zeroed out
//    (bit-deterministic: fp add is commutative, 0+a=a exact).
// ---------------------------------------------------------------------------
__global__ void __launch_bounds__(512) scores_kernel(float* __restrict__ out) {
    __shared__ float s_sm[WAYN * NC];        // 10 KB
    __shared__ float sn_sm[WAYN];
    __shared__ float part[6][8][128];        // 24 KB
    __shared__ float red[128];

    const int n  = blockIdx.x;
    const int fh = blockIdx.y;               // 0..1 spatial half
    const int m0 = n / 15;
    const int qi = n - m0 * 15;
    const int bq = m0 * 20 + SHOTN + qi;
    const int tid = threadIdx.x;

    for (int l = tid; l < WAYN * NC; l += 512) s_sm[l] = g_s[l];
    __syncthreads();

    // warps 0..4: warp w reduces ||s[w]||  (sn read after the next barrier)
    const int wid = tid >> 5, lid = tid & 31;
    if (wid < WAYN) {
        float a = 0.f;
        #pragma unroll
        for (int j = 0; j < NC / 32; j++) {
            float v = s_sm[wid * NC + j * 32 + lid];
            a += v * v;
        }
        #pragma unroll
        for (int o = 16; o > 0; o >>= 1)
            a += __shfl_xor_sync(0xffffffff, a, o);
        if (lid == 0) sn_sm[wid] = fmaxf(sqrtf(a), EPSF);
    }

    const int fp = tid & 63;                 // f-pair index
    const int slice = tid >> 6;              // 0..7
    const int d0 = slice * 64;
    const int f0 = fh * 128 + fp * 2;
    const __nv_bfloat16* xb = g_xh + (size_t)bq * CHW;
    const __nv_bfloat16* Mb = g_M + (size_t)bq * CHW;

    float dot0[WAYN] = {}, dot1[WAYN] = {};
    float q20 = 0.f, q21 = 0.f;
    #pragma unroll 4
    for (int dd = 0; dd < 64; dd++) {
        size_t idx = (size_t)(d0 + dd) * NHW + f0;
        float2 xf = __bfloat1622float2(*(const __nv_bfloat162*)(xb + idx));
        float2 mf = __bfloat1622float2(*(const __nv_bfloat162*)(Mb + idx));
        float qv0 = xf.x * mf.x, qv1 = xf.y * mf.y;
        q20 += qv0 * qv0;
        q21 += qv1 * qv1;
        float sv;
        #pragma unroll
        for (int m = 0; m < WAYN; m++) {
            sv = s_sm[m * NC + d0 + dd];
            dot0[m] += qv0 * sv;
            dot1[m] += qv1 * sv;
        }
    }
    part[0][slice][fp * 2]     = q20;
    part[0][slice][fp * 2 + 1] = q21;
    #pragma unroll
    for (int m = 0; m < WAYN; m++) {
        part[1 + m][slice][fp * 2]     = dot0[m];
        part[1 + m][slice][fp * 2 + 1] = dot1[m];
    }
    __syncthreads();

    float eprob[WAYN];
    if (tid < 128) {
        const int fl = tid;
        float q2 = 0.f;
        #pragma unroll
        for (int s = 0; s < 8; s++) q2 += part[0][s][fl];
        float dot[WAYN];
        #pragma unroll
        for (int m = 0; m < WAYN; m++) {
            float dsum = 0.f;
            #pragma unroll
            for (int s = 0; s < 8; s++) dsum += part[1 + m][s][fl];
            dot[m] = dsum;
        }
        const float qn = fmaxf(sqrtf(q2), EPSF);
        float sc[WAYN], mxv = -3.4e38f;
        #pragma unroll
        for (int m = 0; m < WAYN; m++) {
            sc[m] = SCALEF * dot[m] / (qn * sn_sm[m]);
            mxv = fmaxf(mxv, sc[m]);
        }
        float ssum = 0.f;
        #pragma unroll
        for (int m = 0; m < WAYN; m++) { eprob[m] = __expf(sc[m] - mxv); ssum += eprob[m]; }
        const float inv = 1.f / ssum;
        #pragma unroll
        for (int m = 0; m < WAYN; m++) eprob[m] *= inv;
    }

    for (int m = 0; m < WAYN; m++) {
        __syncthreads();
        if (tid < 128) red[tid] = eprob[m];
        __syncthreads();
        for (int st = 64; st > 0; st >>= 1) {
            if (tid < st) red[tid] += red[tid + st];
            __syncthreads();
        }
        if (tid == 0) atomicAdd(&out[n * WAYN + m], red[0] * (1.f / NHW));
    }
}

// ---------------------------------------------------------------------------
extern "C" void kernel_launch(void* const* d_in, const int* in_sizes, int n_in,
                              void* d_out, int out_size) {
    const float* x    = (const float*)d_in[0];   // (100, 512, 16, 16)
    const float* Wm   = (const float*)d_in[1];   // (512, 512)
    const float* bias = (const float*)d_in[2];   // (512,)
    float* out = (float*)d_out;                  // (75, 5)

    static int smem_set = 0;
    if (!smem_set) {
        cudaFuncSetAttribute(gemm_tc, cudaFuncAttributeMaxDynamicSharedMemorySize, GEMM_SMEM);
        smem_set = 1;
    }

    cudaMemsetAsync(out, 0, (size_t)out_size * sizeof(float));   // capturable memset node
    split_all<<<WBLOCKS + NB * CHW / 1024, 256>>>(x, Wm);
    gemm_tc<<<dim3(NHW / 128, NC / 128, NB), 256, GEMM_SMEM>>>(bias);
    protos<<<dim3(WAYN, NC), 160>>>();
    scores_kernel<<<dim3(NQ, 2), 512>>>(out);
}

// round 15
// speedup vs baseline: 1.8916x; 1.1680x over previous
#include <cuda_runtime.h>
#include <cuda_bf16.h>
#include <math.h>
#include <cstdint>

#define NB   100
#define NC   512
#define NHW  256
#define CHW  (NC*NHW)          // 131072
#define WAYN 5
#define SHOTN 5
#define NQ   75
#define SCALEF 10.0f
#define EPSF 1e-8f

// Scratch (static device globals — no runtime allocation)
__device__ __nv_bfloat16 g_M[NB*CHW];         // exp(conv logits + bias), bf16
__device__ float g_part[NB*8];                // per-tile partial sum(exp)
__device__ float g_s[WAYN*NC];                // prototypes
__device__ __nv_bfloat16 g_Wh[NC*NC];         // W (bf16)
__device__ __nv_bfloat16 g_xh[NB*CHW];        // x (bf16)

// ---------------------------------------------------------------------------
// Fused fp32 -> bf16 conversion: blocks [0,256) do W, rest do x.
// ---------------------------------------------------------------------------
__device__ __forceinline__ uint32_t pack_bf2(__nv_bfloat16 a, __nv_bfloat16 b) {
    return (uint32_t)__bfloat16_as_ushort(a) | ((uint32_t)__bfloat16_as_ushort(b) << 16);
}

#define WBLOCKS (NC * NC / 1024)              // 256

__global__ void split_all(const float* __restrict__ x, const float* __restrict__ Wm) {
    const float* src;
    __nv_bfloat16* dst;
    size_t i;
    if (blockIdx.x < WBLOCKS) {
        i = ((size_t)blockIdx.x * 256 + threadIdx.x) * 4;
        src = Wm; dst = g_Wh;
    } else {
        i = ((size_t)(blockIdx.x - WBLOCKS) * 256 + threadIdx.x) * 4;
        src = x; dst = g_xh;
    }
    float4 v = *(const float4*)(src + i);
    uint2 ph = {pack_bf2(__float2bfloat16(v.x), __float2bfloat16(v.y)),
                pack_bf2(__float2bfloat16(v.z), __float2bfloat16(v.w))};
    *(uint2*)(dst + i) = ph;
}

// ---------------------------------------------------------------------------
// 1) Pure bf16 mma.sync GEMM, K = 512. 3-stage cp.async pipeline.
//    CTA tile 128(M) x 128(N) x 32(K), 8 warps (2m x 4n), warp tile 64x32.
//    Epilogue stores bf16 exp(logit+bias) and fp32 per-tile partial sums.
// ---------------------------------------------------------------------------
#define KCHUNK   32
#define NCHUNKS  16   // 512 / 32
#define AS_STRIDE 56
#define BS_STRIDE 136
#define AS_BYTES  (128 * AS_STRIDE * 2)      // 14336
#define BS_BYTES  (32 * BS_STRIDE * 2)       // 8704
#define STAGE_BYTES (AS_BYTES + BS_BYTES)    // 23040
#define GEMM_SMEM (3 * STAGE_BYTES)          // 69120

__global__ void __launch_bounds__(256) gemm_tc(const float* __restrict__ bias) {
    extern __shared__ __align__(16) char dynsmem[];

    const int tid = threadIdx.x;
    const int wid = tid >> 5, lid = tid & 31;
    const int bn = blockIdx.x * 128;      // n tile offset (hw)
    const int mo = blockIdx.y * 128;      // m tile offset (outC)
    const int b  = blockIdx.z;

    const int warp_m = wid >> 2;          // 0..1
    const int warp_n = wid & 3;           // 0..3
    const int m_base = warp_m * 64;
    const int n_base = warp_n * 32;

    const __nv_bfloat16* xh_b = g_xh + (size_t)b * CHW;

    float acc[4][4][4] = {};

    auto issue = [&](int chunk, int buf) {
        const int k0 = chunk * KCHUNK;
        __nv_bfloat16* As = (__nv_bfloat16*)(dynsmem + buf * STAGE_BYTES);
        __nv_bfloat16* Bs = (__nv_bfloat16*)(dynsmem + buf * STAGE_BYTES + AS_BYTES);
        #pragma unroll
        for (int i = 0; i < 2; i++) {           // A: 128 rows x 32 k
            int idx = tid + i * 256;
            int row = idx >> 2, s = idx & 3;
            const void* src = g_Wh + (size_t)(mo + row) * NC + k0 + s * 8;
            uint32_t dst = (uint32_t)__cvta_generic_to_shared(As + row * AS_STRIDE + s * 8);
            asm volatile("cp.async.cg.shared.global [%0], [%1], 16;" :: "r"(dst), "l"(src));
        }
        #pragma unroll
        for (int i = 0; i < 2; i++) {           // B: 32 k-rows x 128 n
            int idx = tid + i * 256;
            int row = idx >> 4, s = idx & 15;
            const void* src = xh_b + (size_t)(k0 + row) * NHW + bn + s * 8;
            uint32_t dst = (uint32_t)__cvta_generic_to_shared(Bs + row * BS_STRIDE + s * 8);
            asm volatile("cp.async.cg.shared.global [%0], [%1], 16;" :: "r"(dst), "l"(src));
        }
        asm volatile("cp.async.commit_group;");
    };

    issue(0, 0);
    issue(1, 1);

    int buf = 0;
    for (int c = 0; c < NCHUNKS; c++) {
        if (c == NCHUNKS - 1) asm volatile("cp.async.wait_group 0;");
        else                  asm volatile("cp.async.wait_group 1;");
        __syncthreads();
        if (c + 2 < NCHUNKS) {
            int nb = buf + 2; if (nb >= 3) nb -= 3;
            issue(c + 2, nb);
        }

        const __nv_bfloat16* As = (const __nv_bfloat16*)(dynsmem + buf * STAGE_BYTES);
        const __nv_bfloat16* Bs = (const __nv_bfloat16*)(dynsmem + buf * STAGE_BYTES + AS_BYTES);

        #pragma unroll
        for (int kk = 0; kk < 2; kk++) {
            const int k16 = kk * 16;
            uint32_t af[4][4];
            #pragma unroll
            for (int mi = 0; mi < 4; mi++) {
                uint32_t addr = (uint32_t)__cvta_generic_to_shared(
                    As + (m_base + mi * 16 + (lid & 15)) * AS_STRIDE + k16 + (lid >> 4) * 8);
                asm volatile("ldmatrix.sync.aligned.m8n8.x4.shared.b16 {%0,%1,%2,%3}, [%4];"
                    : "=r"(af[mi][0]), "=r"(af[mi][1]), "=r"(af[mi][2]), "=r"(af[mi][3])
                    : "r"(addr));
            }
            uint32_t bfr[4][2];
            #pragma unroll
            for (int njp = 0; njp < 2; njp++) {
                uint32_t addr = (uint32_t)__cvta_generic_to_shared(
                    Bs + (k16 + (lid & 15)) * BS_STRIDE + n_base + njp * 16 + (lid >> 4) * 8);
                asm volatile("ldmatrix.sync.aligned.m8n8.x4.trans.shared.b16 {%0,%1,%2,%3}, [%4];"
                    : "=r"(bfr[2*njp][0]), "=r"(bfr[2*njp][1]),
                      "=r"(bfr[2*njp+1][0]), "=r"(bfr[2*njp+1][1])
                    : "r"(addr));
            }
            #pragma unroll
            for (int mi = 0; mi < 4; mi++)
                #pragma unroll
                for (int nj = 0; nj < 4; nj++)
                    asm volatile(
                        "mma.sync.aligned.m16n8k16.row.col.f32.bf16.bf16.f32 "
                        "{%0,%1,%2,%3}, {%4,%5,%6,%7}, {%8,%9}, {%0,%1,%2,%3};"
                        : "+f"(acc[mi][nj][0]), "+f"(acc[mi][nj][1]),
                          "+f"(acc[mi][nj][2]), "+f"(acc[mi][nj][3])
                        : "r"(af[mi][0]), "r"(af[mi][1]), "r"(af[mi][2]), "r"(af[mi][3]),
                          "r"(bfr[nj][0]), "r"(bfr[nj][1]));
        }
        buf++; if (buf == 3) buf = 0;
    }

    // Epilogue: store bf16 exp(logit + bias), fused fp32 partial sum(exp)
    __nv_bfloat16* Mb = g_M + (size_t)b * CHW;
    float esum = 0.f;
    #pragma unroll
    for (int mi = 0; mi < 4; mi++) {
        int r0 = mo + m_base + mi * 16 + (lid >> 2);
        float b0 = bias[r0], b1 = bias[r0 + 8];
        #pragma unroll
        for (int nj = 0; nj < 4; nj++) {
            int col = bn + n_base + nj * 8 + (lid & 3) * 2;
            float e00 = __expf(acc[mi][nj][0] + b0);
            float e01 = __expf(acc[mi][nj][1] + b0);
            float e10 = __expf(acc[mi][nj][2] + b1);
            float e11 = __expf(acc[mi][nj][3] + b1);
            esum += e00 + e01 + e10 + e11;
            *(uint32_t*)(Mb + (size_t)r0 * NHW + col) =
                pack_bf2(__float2bfloat16(e00), __float2bfloat16(e01));
            *(uint32_t*)(Mb + (size_t)(r0 + 8) * NHW + col) =
                pack_bf2(__float2bfloat16(e10), __float2bfloat16(e11));
        }
    }
    __syncthreads();                 // all async groups done; safe to reuse smem
    float* red = (float*)dynsmem;
    red[tid] = esum;
    __syncthreads();
    for (int s = 128; s > 0; s >>= 1) {
        if (tid < s) red[tid] += red[tid + s];
        __syncthreads();
    }
    if (tid == 0)
        g_part[b * 8 + blockIdx.y * 2 + blockIdx.x] = red[0];
}

// ---------------------------------------------------------------------------
// 2) Prototypes (fused mask): s[m,d] = mean over shots,hw of x*Me*inv_sb
//    160 threads = 5 warps; warp = shot; each thread 8 bf16 pairs (uint4).
// ---------------------------------------------------------------------------
__global__ void __launch_bounds__(160) protos() {
    __shared__ float inv_sm[SHOTN];
    __shared__ float wsum[SHOTN];
    const int m = blockIdx.x;
    const int d = blockIdx.y;
    const int tid = threadIdx.x;
    const int sb = tid >> 5;           // warp = shot
    const int lid = tid & 31;

    if (tid < SHOTN) {
        float s = 0.f;
        #pragma unroll
        for (int t = 0; t < 8; t++) s += g_part[(m * 20 + tid) * 8 + t];
        inv_sm[tid] = 1.f / s;
    }
    __syncthreads();

    const size_t base = (size_t)(m * 20 + sb) * CHW + (size_t)d * NHW + lid * 8;
    uint4 xv = *(const uint4*)(g_xh + base);
    uint4 mv = *(const uint4*)(g_M + base);
    float s = 0.f;
    const uint32_t* xp = (const uint32_t*)&xv;
    const uint32_t* mp = (const uint32_t*)&mv;
    #pragma unroll
    for (int j = 0; j < 4; j++) {
        float2 xf = __bfloat1622float2(*(const __nv_bfloat162*)&xp[j]);
        float2 mf = __bfloat1622float2(*(const __nv_bfloat162*)&mp[j]);
        s += xf.x * mf.x + xf.y * mf.y;
    }
    s *= inv_sm[sb];

    #pragma unroll
    for (int o = 16; o > 0; o >>= 1)
        s += __shfl_xor_sync(0xffffffff, s, o);
    if (lid == 0) wsum[sb] = s;
    __syncthreads();
    if (tid == 0) {
        float t = 0.f;
        #pragma unroll
        for (int w = 0; w < SHOTN; w++) t += wsum[w];
        g_s[m * NC + d] = t * (1.f / (SHOTN * NHW));
    }
}

// ---------------------------------------------------------------------------
// 3) Cosine scores + class softmax + spatial mean.
//    Grid (NQ, 2), 1024 threads: thread = (d-slice 0..15, f-pair 0..63).
//    Each thread's serial chain is 32 L2 loads (was 64). Tail reduction via
//    one eprob staging + 5 concurrent warp shfl-reductions (2 barriers).
//    Cross-block spatial mean via 2-way atomicAdd into zeroed out
//    (bit-deterministic: fp add commutative, 0+a=a exact).
// ---------------------------------------------------------------------------
__global__ void __launch_bounds__(1024) scores_kernel(float* __restrict__ out) {
    __shared__ float s_sm[WAYN * NC];        // 10 KB
    __shared__ float sn_sm[WAYN];
    __shared__ float part[6][16][128];       // 48 KB
    __shared__ float ered[WAYN][128];        // 2.5 KB

    const int n  = blockIdx.x;
    const int fh = blockIdx.y;               // 0..1 spatial half
    const int m0 = n / 15;
    const int qi = n - m0 * 15;
    const int bq = m0 * 20 + SHOTN + qi;
    const int tid = threadIdx.x;

    for (int l = tid; l < WAYN * NC; l += 1024) s_sm[l] = g_s[l];
    __syncthreads();

    // warps 0..4: warp w reduces ||s[w]||  (sn read after the next barrier)
    const int wid = tid >> 5, lid = tid & 31;
    if (wid < WAYN) {
        float a = 0.f;
        #pragma unroll
        for (int j = 0; j < NC / 32; j++) {
            float v = s_sm[wid * NC + j * 32 + lid];
            a += v * v;
        }
        #pragma unroll
        for (int o = 16; o > 0; o >>= 1)
            a += __shfl_xor_sync(0xffffffff, a, o);
        if (lid == 0) sn_sm[wid] = fmaxf(sqrtf(a), EPSF);
    }

    const int fp = tid & 63;                 // f-pair index (128 f per block)
    const int slice = tid >> 6;              // 0..15, 32 d each
    const int d0 = slice * 32;
    const int f0 = fh * 128 + fp * 2;
    const __nv_bfloat16* xb = g_xh + (size_t)bq * CHW;
    const __nv_bfloat16* Mb = g_M + (size_t)bq * CHW;

    float dot0[WAYN] = {}, dot1[WAYN] = {};
    float q20 = 0.f, q21 = 0.f;
    #pragma unroll 8
    for (int dd = 0; dd < 32; dd++) {
        size_t idx = (size_t)(d0 + dd) * NHW + f0;
        float2 xf = __bfloat1622float2(*(const __nv_bfloat162*)(xb + idx));
        float2 mf = __bfloat1622float2(*(const __nv_bfloat162*)(Mb + idx));
        float qv0 = xf.x * mf.x, qv1 = xf.y * mf.y;
        q20 += qv0 * qv0;
        q21 += qv1 * qv1;
        float sv;
        #pragma unroll
        for (int m = 0; m < WAYN; m++) {
            sv = s_sm[m * NC + d0 + dd];
            dot0[m] += qv0 * sv;
            dot1[m] += qv1 * sv;
        }
    }
    part[0][slice][fp * 2]     = q20;
    part[0][slice][fp * 2 + 1] = q21;
    #pragma unroll
    for (int m = 0; m < WAYN; m++) {
        part[1 + m][slice][fp * 2]     = dot0[m];
        part[1 + m][slice][fp * 2 + 1] = dot1[m];
    }
    __syncthreads();

    if (tid < 128) {
        const int fl = tid;
        float q2 = 0.f;
        #pragma unroll
        for (int s = 0; s < 16; s++) q2 += part[0][s][fl];
        float dot[WAYN];
        #pragma unroll
        for (int m = 0; m < WAYN; m++) {
            float dsum = 0.f;
            #pragma unroll
            for (int s = 0; s < 16; s++) dsum += part[1 + m][s][fl];
            dot[m] = dsum;
        }
        const float qn = fmaxf(sqrtf(q2), EPSF);
        float sc[WAYN], mxv = -3.4e38f;
        #pragma unroll
        for (int m = 0; m < WAYN; m++) {
            sc[m] = SCALEF * dot[m] / (qn * sn_sm[m]);
            mxv = fmaxf(mxv, sc[m]);
        }
        float eprob[WAYN], ssum = 0.f;
        #pragma unroll
        for (int m = 0; m < WAYN; m++) { eprob[m] = __expf(sc[m] - mxv); ssum += eprob[m]; }
        const float inv = 1.f / ssum;
        #pragma unroll
        for (int m = 0; m < WAYN; m++) ered[m][fl] = eprob[m] * inv;
    }
    __syncthreads();

    // 5 warps reduce the 5 classes concurrently (128 values each), shfl only.
    if (wid < WAYN) {
        float a = ered[wid][lid] + ered[wid][lid + 32]
                + ered[wid][lid + 64] + ered[wid][lid + 96];
        #pragma unroll
        for (int o = 16; o > 0; o >>= 1)
            a += __shfl_xor_sync(0xffffffff, a, o);
        if (lid == 0) atomicAdd(&out[n * WAYN + wid], a * (1.f / NHW));
    }
}

// ---------------------------------------------------------------------------
extern "C" void kernel_launch(void* const* d_in, const int* in_sizes, int n_in,
                              void* d_out, int out_size) {
    const float* x    = (const float*)d_in[0];   // (100, 512, 16, 16)
    const float* Wm   = (const float*)d_in[1];   // (512, 512)
    const float* bias = (const float*)d_in[2];   // (512,)
    float* out = (float*)d_out;                  // (75, 5)

    static int smem_set = 0;
    if (!smem_set) {
        cudaFuncSetAttribute(gemm_tc, cudaFuncAttributeMaxDynamicSharedMemorySize, GEMM_SMEM);
        smem_set = 1;
    }

    cudaMemsetAsync(out, 0, (size_t)out_size * sizeof(float));   // capturable memset node
    split_all<<<WBLOCKS + NB * CHW / 1024, 256>>>(x, Wm);
    gemm_tc<<<dim3(NHW / 128, NC / 128, NB), 256, GEMM_SMEM>>>(bias);
    protos<<<dim3(WAYN, NC), 160>>>();
    scores_kernel<<<dim3(NQ, 2), 1024>>>(out);
}

// round 16
// speedup vs baseline: 1.9143x; 1.0120x over previous
#include <cuda_runtime.h>
#include <cuda_bf16.h>
#include <math.h>
#include <cstdint>

#define NB   100
#define NC   512
#define NHW  256
#define CHW  (NC*NHW)          // 131072
#define WAYN 5
#define SHOTN 5
#define NQ   75
#define SCALEF 10.0f
#define EPSF 1e-8f

// Scratch (static device globals — no runtime allocation)
__device__ __nv_bfloat16 g_M[NB*CHW];         // y = x * exp(logit+bias), bf16 (unnormalized mask product)
__device__ float g_part[NB*8];                // per-tile partial sum(exp)
__device__ float g_s[WAYN*NC];                // prototypes
__device__ __nv_bfloat16 g_Wh[NC*NC];         // W (bf16)
__device__ __nv_bfloat16 g_xh[NB*CHW];        // x (bf16)

// ---------------------------------------------------------------------------
// Fused fp32 -> bf16 conversion: blocks [0,256) do W, rest do x.
// ---------------------------------------------------------------------------
__device__ __forceinline__ uint32_t pack_bf2(__nv_bfloat16 a, __nv_bfloat16 b) {
    return (uint32_t)__bfloat16_as_ushort(a) | ((uint32_t)__bfloat16_as_ushort(b) << 16);
}

#define WBLOCKS (NC * NC / 1024)              // 256

__global__ void split_all(const float* __restrict__ x, const float* __restrict__ Wm) {
    const float* src;
    __nv_bfloat16* dst;
    size_t i;
    if (blockIdx.x < WBLOCKS) {
        i = ((size_t)blockIdx.x * 256 + threadIdx.x) * 4;
        src = Wm; dst = g_Wh;
    } else {
        i = ((size_t)(blockIdx.x - WBLOCKS) * 256 + threadIdx.x) * 4;
        src = x; dst = g_xh;
    }
    float4 v = *(const float4*)(src + i);
    uint2 ph = {pack_bf2(__float2bfloat16(v.x), __float2bfloat16(v.y)),
                pack_bf2(__float2bfloat16(v.z), __float2bfloat16(v.w))};
    *(uint2*)(dst + i) = ph;
}

// ---------------------------------------------------------------------------
// 1) Pure bf16 mma.sync GEMM, K = 512. 3-stage cp.async pipeline.
//    CTA tile 128(M) x 128(N) x 32(K), 8 warps (2m x 4n), warp tile 64x32.
//    Epilogue: e = exp(logit+bias); stores y = x*e (bf16) + fp32 partial sums of e.
// ---------------------------------------------------------------------------
#define KCHUNK   32
#define NCHUNKS  16   // 512 / 32
#define AS_STRIDE 56
#define BS_STRIDE 136
#define AS_BYTES  (128 * AS_STRIDE * 2)      // 14336
#define BS_BYTES  (32 * BS_STRIDE * 2)       // 8704
#define STAGE_BYTES (AS_BYTES + BS_BYTES)    // 23040
#define GEMM_SMEM (3 * STAGE_BYTES)          // 69120

__global__ void __launch_bounds__(256) gemm_tc(const float* __restrict__ bias) {
    extern __shared__ __align__(16) char dynsmem[];

    const int tid = threadIdx.x;
    const int wid = tid >> 5, lid = tid & 31;
    const int bn = blockIdx.x * 128;      // n tile offset (hw)
    const int mo = blockIdx.y * 128;      // m tile offset (outC)
    const int b  = blockIdx.z;

    const int warp_m = wid >> 2;          // 0..1
    const int warp_n = wid & 3;           // 0..3
    const int m_base = warp_m * 64;
    const int n_base = warp_n * 32;

    const __nv_bfloat16* xh_b = g_xh + (size_t)b * CHW;

    float acc[4][4][4] = {};

    auto issue = [&](int chunk, int buf) {
        const int k0 = chunk * KCHUNK;
        __nv_bfloat16* As = (__nv_bfloat16*)(dynsmem + buf * STAGE_BYTES);
        __nv_bfloat16* Bs = (__nv_bfloat16*)(dynsmem + buf * STAGE_BYTES + AS_BYTES);
        #pragma unroll
        for (int i = 0; i < 2; i++) {           // A: 128 rows x 32 k
            int idx = tid + i * 256;
            int row = idx >> 2, s = idx & 3;
            const void* src = g_Wh + (size_t)(mo + row) * NC + k0 + s * 8;
            uint32_t dst = (uint32_t)__cvta_generic_to_shared(As + row * AS_STRIDE + s * 8);
            asm volatile("cp.async.cg.shared.global [%0], [%1], 16;" :: "r"(dst), "l"(src));
        }
        #pragma unroll
        for (int i = 0; i < 2; i++) {           // B: 32 k-rows x 128 n
            int idx = tid + i * 256;
            int row = idx >> 4, s = idx & 15;
            const void* src = xh_b + (size_t)(k0 + row) * NHW + bn + s * 8;
            uint32_t dst = (uint32_t)__cvta_generic_to_shared(Bs + row * BS_STRIDE + s * 8);
            asm volatile("cp.async.cg.shared.global [%0], [%1], 16;" :: "r"(dst), "l"(src));
        }
        asm volatile("cp.async.commit_group;");
    };

    issue(0, 0);
    issue(1, 1);

    int buf = 0;
    for (int c = 0; c < NCHUNKS; c++) {
        if (c == NCHUNKS - 1) asm volatile("cp.async.wait_group 0;");
        else                  asm volatile("cp.async.wait_group 1;");
        __syncthreads();
        if (c + 2 < NCHUNKS) {
            int nb = buf + 2; if (nb >= 3) nb -= 3;
            issue(c + 2, nb);
        }

        const __nv_bfloat16* As = (const __nv_bfloat16*)(dynsmem + buf * STAGE_BYTES);
        const __nv_bfloat16* Bs = (const __nv_bfloat16*)(dynsmem + buf * STAGE_BYTES + AS_BYTES);

        #pragma unroll
        for (int kk = 0; kk < 2; kk++) {
            const int k16 = kk * 16;
            uint32_t af[4][4];
            #pragma unroll
            for (int mi = 0; mi < 4; mi++) {
                uint32_t addr = (uint32_t)__cvta_generic_to_shared(
                    As + (m_base + mi * 16 + (lid & 15)) * AS_STRIDE + k16 + (lid >> 4) * 8);
                asm volatile("ldmatrix.sync.aligned.m8n8.x4.shared.b16 {%0,%1,%2,%3}, [%4];"
                    : "=r"(af[mi][0]), "=r"(af[mi][1]), "=r"(af[mi][2]), "=r"(af[mi][3])
                    : "r"(addr));
            }
            uint32_t bfr[4][2];
            #pragma unroll
            for (int njp = 0; njp < 2; njp++) {
                uint32_t addr = (uint32_t)__cvta_generic_to_shared(
                    Bs + (k16 + (lid & 15)) * BS_STRIDE + n_base + njp * 16 + (lid >> 4) * 8);
                asm volatile("ldmatrix.sync.aligned.m8n8.x4.trans.shared.b16 {%0,%1,%2,%3}, [%4];"
                    : "=r"(bfr[2*njp][0]), "=r"(bfr[2*njp][1]),
                      "=r"(bfr[2*njp+1][0]), "=r"(bfr[2*njp+1][1])
                    : "r"(addr));
            }
            #pragma unroll
            for (int mi = 0; mi < 4; mi++)
                #pragma unroll
                for (int nj = 0; nj < 4; nj++)
                    asm volatile(
                        "mma.sync.aligned.m16n8k16.row.col.f32.bf16.bf16.f32 "
                        "{%0,%1,%2,%3}, {%4,%5,%6,%7}, {%8,%9}, {%0,%1,%2,%3};"
                        : "+f"(acc[mi][nj][0]), "+f"(acc[mi][nj][1]),
                          "+f"(acc[mi][nj][2]), "+f"(acc[mi][nj][3])
                        : "r"(af[mi][0]), "r"(af[mi][1]), "r"(af[mi][2]), "r"(af[mi][3]),
                          "r"(bfr[nj][0]), "r"(bfr[nj][1]));
        }
        buf++; if (buf == 3) buf = 0;
    }

    // Epilogue: e = exp(logit + bias); store y = x*e (bf16); partial sum of e.
    __nv_bfloat16* Mb = g_M + (size_t)b * CHW;
    float esum = 0.f;
    #pragma unroll
    for (int mi = 0; mi < 4; mi++) {
        int r0 = mo + m_base + mi * 16 + (lid >> 2);
        float b0 = bias[r0], b1 = bias[r0 + 8];
        #pragma unroll
        for (int nj = 0; nj < 4; nj++) {
            int col = bn + n_base + nj * 8 + (lid & 3) * 2;
            float e00 = __expf(acc[mi][nj][0] + b0);
            float e01 = __expf(acc[mi][nj][1] + b0);
            float e10 = __expf(acc[mi][nj][2] + b1);
            float e11 = __expf(acc[mi][nj][3] + b1);
            esum += e00 + e01 + e10 + e11;
            size_t i0 = (size_t)r0 * NHW + col;
            size_t i1 = (size_t)(r0 + 8) * NHW + col;
            float2 x0 = __bfloat1622float2(*(const __nv_bfloat162*)(xh_b + i0));
            float2 x1 = __bfloat1622float2(*(const __nv_bfloat162*)(xh_b + i1));
            *(uint32_t*)(Mb + i0) =
                pack_bf2(__float2bfloat16(x0.x * e00), __float2bfloat16(x0.y * e01));
            *(uint32_t*)(Mb + i1) =
                pack_bf2(__float2bfloat16(x1.x * e10), __float2bfloat16(x1.y * e11));
        }
    }
    __syncthreads();                 // all async groups done; safe to reuse smem
    float* red = (float*)dynsmem;
    red[tid] = esum;
    __syncthreads();
    for (int s = 128; s > 0; s >>= 1) {
        if (tid < s) red[tid] += red[tid + s];
        __syncthreads();
    }
    if (tid == 0)
        g_part[b * 8 + blockIdx.y * 2 + blockIdx.x] = red[0];
}

// ---------------------------------------------------------------------------
// 2) Prototypes: s[m,d] = mean over shots,hw of y*inv_sb  (y = x*e from gemm)
//    160 threads = 5 warps; warp = shot; each thread 8 bf16 (uint4).
// ---------------------------------------------------------------------------
__global__ void __launch_bounds__(160) protos() {
    __shared__ float inv_sm[SHOTN];
    __shared__ float wsum[SHOTN];
    const int m = blockIdx.x;
    const int d = blockIdx.y;
    const int tid = threadIdx.x;
    const int sb = tid >> 5;           // warp = shot
    const int lid = tid & 31;

    if (tid < SHOTN) {
        float s = 0.f;
        #pragma unroll
        for (int t = 0; t < 8; t++) s += g_part[(m * 20 + tid) * 8 + t];
        inv_sm[tid] = 1.f / s;
    }
    __syncthreads();

    const size_t base = (size_t)(m * 20 + sb) * CHW + (size_t)d * NHW + lid * 8;
    uint4 yv = *(const uint4*)(g_M + base);
    float s = 0.f;
    const uint32_t* yp = (const uint32_t*)&yv;
    #pragma unroll
    for (int j = 0; j < 4; j++) {
        float2 yf = __bfloat1622float2(*(const __nv_bfloat162*)&yp[j]);
        s += yf.x + yf.y;
    }
    s *= inv_sm[sb];

    #pragma unroll
    for (int o = 16; o > 0; o >>= 1)
        s += __shfl_xor_sync(0xffffffff, s, o);
    if (lid == 0) wsum[sb] = s;
    __syncthreads();
    if (tid == 0) {
        float t = 0.f;
        #pragma unroll
        for (int w = 0; w < SHOTN; w++) t += wsum[w];
        g_s[m * NC + d] = t * (1.f / (SHOTN * NHW));
    }
}

// ---------------------------------------------------------------------------
// 3) Cosine scores + class softmax + spatial mean.
//    Grid (NQ, 2), 1024 threads: thread = (d-slice 0..15, f-pair 0..63).
//    qv = y directly (normalizer cancels in cosine) — ONE load per iteration.
//    Tail: eprob staging + 5 concurrent warp shfl-reductions.
//    Cross-block spatial mean via 2-way atomicAdd into zeroed out
//    (bit-deterministic: fp add commutative, 0+a=a exact).
// ---------------------------------------------------------------------------
__global__ void __launch_bounds__(1024) scores_kernel(float* __restrict__ out) {
    __shared__ float s_sm[WAYN * NC];        // 10 KB
    __shared__ float sn_sm[WAYN];
    __shared__ float part[6][16][128];       // 48 KB
    __shared__ float ered[WAYN][128];        // 2.5 KB

    const int n  = blockIdx.x;
    const int fh = blockIdx.y;               // 0..1 spatial half
    const int m0 = n / 15;
    const int qi = n - m0 * 15;
    const int bq = m0 * 20 + SHOTN + qi;
    const int tid = threadIdx.x;

    for (int l = tid; l < WAYN * NC; l += 1024) s_sm[l] = g_s[l];
    __syncthreads();

    // warps 0..4: warp w reduces ||s[w]||  (sn read after the next barrier)
    const int wid = tid >> 5, lid = tid & 31;
    if (wid < WAYN) {
        float a = 0.f;
        #pragma unroll
        for (int j = 0; j < NC / 32; j++) {
            float v = s_sm[wid * NC + j * 32 + lid];
            a += v * v;
        }
        #pragma unroll
        for (int o = 16; o > 0; o >>= 1)
            a += __shfl_xor_sync(0xffffffff, a, o);
        if (lid == 0) sn_sm[wid] = fmaxf(sqrtf(a), EPSF);
    }

    const int fp = tid & 63;                 // f-pair index (128 f per block)
    const int slice = tid >> 6;              // 0..15, 32 d each
    const int d0 = slice * 32;
    const int f0 = fh * 128 + fp * 2;
    const __nv_bfloat16* Yb = g_M + (size_t)bq * CHW;

    float dot0[WAYN] = {}, dot1[WAYN] = {};
    float q20 = 0.f, q21 = 0.f;
    #pragma unroll 8
    for (int dd = 0; dd < 32; dd++) {
        size_t idx = (size_t)(d0 + dd) * NHW + f0;
        float2 yf = __bfloat1622float2(*(const __nv_bfloat162*)(Yb + idx));
        q20 += yf.x * yf.x;
        q21 += yf.y * yf.y;
        float sv;
        #pragma unroll
        for (int m = 0; m < WAYN; m++) {
            sv = s_sm[m * NC + d0 + dd];
            dot0[m] += yf.x * sv;
            dot1[m] += yf.y * sv;
        }
    }
    part[0][slice][fp * 2]     = q20;
    part[0][slice][fp * 2 + 1] = q21;
    #pragma unroll
    for (int m = 0; m < WAYN; m++) {
        part[1 + m][slice][fp * 2]     = dot0[m];
        part[1 + m][slice][fp * 2 + 1] = dot1[m];
    }
    __syncthreads();

    if (tid < 128) {
        const int fl = tid;
        float q2 = 0.f;
        #pragma unroll
        for (int s = 0; s < 16; s++) q2 += part[0][s][fl];
        float dot[WAYN];
        #pragma unroll
        for (int m = 0; m < WAYN; m++) {
            float dsum = 0.f;
            #pragma unroll
            for (int s = 0; s < 16; s++) dsum += part[1 + m][s][fl];
            dot[m] = dsum;
        }
        const float qn = fmaxf(sqrtf(q2), EPSF);
        float sc[WAYN], mxv = -3.4e38f;
        #pragma unroll
        for (int m = 0; m < WAYN; m++) {
            sc[m] = SCALEF * dot[m] / (qn * sn_sm[m]);
            mxv = fmaxf(mxv, sc[m]);
        }
        float eprob[WAYN], ssum = 0.f;
        #pragma unroll
        for (int m = 0; m < WAYN; m++) { eprob[m] = __expf(sc[m] - mxv); ssum += eprob[m]; }
        const float inv = 1.f / ssum;
        #pragma unroll
        for (int m = 0; m < WAYN; m++) ered[m][fl] = eprob[m] * inv;
    }
    __syncthreads();

    // 5 warps reduce the 5 classes concurrently (128 values each), shfl only.
    if (wid < WAYN) {
        float a = ered[wid][lid] + ered[wid][lid + 32]
                + ered[wid][lid + 64] + ered[wid][lid + 96];
        #pragma unroll
        for (int o = 16; o > 0; o >>= 1)
            a += __shfl_xor_sync(0xffffffff, a, o);
        if (lid == 0) atomicAdd(&out[n * WAYN + wid], a * (1.f / NHW));
    }
}

// ---------------------------------------------------------------------------
extern "C" void kernel_launch(void* const* d_in, const int* in_sizes, int n_in,
                              void* d_out, int out_size) {
    const float* x    = (const float*)d_in[0];   // (100, 512, 16, 16)
    const float* Wm   = (const float*)d_in[1];   // (512, 512)
    const float* bias = (const float*)d_in[2];   // (512,)
    float* out = (float*)d_out;                  // (75, 5)

    static int smem_set = 0;
    if (!smem_set) {
        cudaFuncSetAttribute(gemm_tc, cudaFuncAttributeMaxDynamicSharedMemorySize, GEMM_SMEM);
        smem_set = 1;
    }

    cudaMemsetAsync(out, 0, (size_t)out_size * sizeof(float));   // capturable memset node
    split_all<<<WBLOCKS + NB * CHW / 1024, 256>>>(x, Wm);
    gemm_tc<<<dim3(NHW / 128, NC / 128, NB), 256, GEMM_SMEM>>>(bias);
    protos<<<dim3(WAYN, NC), 160>>>();
    scores_kernel<<<dim3(NQ, 2), 1024>>>(out);
}